// round 5
// baseline (speedup 1.0000x reference)
#include <cuda_runtime.h>
#include <cuda_bf16.h>
#include <cstdint>

#define NB   10
#define C    64
#define HW   16384
#define KCB  512
#define NG   32
#define TOKT 256
#define THREADS 256

// ---- smem layout (bytes from dynamic base) ----
// X rows padded to 144B (72 bf16) for conflict-free ldmatrix (4-bank row step)
#define XH_OFF   0                // 256 x 144B = 36864
#define XL_OFF   36864
#define WB_OFF   73728            // 2 stages x (4 planes x 9216B)
#define SB_OFF   147456           // sbias 512 f32
#define ZR_OFF   149504           // zrow 256 f32
#define WZB_OFF  150528           // wz_b 64 f32
#define SMEM_TOTAL 150784
// epilogue y-stage reuses [0 .. 66560): 64 rows x 260 f32

// ---------------- device-global scratch ----------------
__device__ float g_mean[NB * NG], g_rstd[NB * NG];
__device__ float g_scA[NB * C], g_bias2[NB * C];
__device__ float g_G[KCB * C];                                  // [k][c], incl 0.125*log2e
__device__ float g_sbias[NB * KCB];                             // incl 0.125*log2e
__device__ __align__(16) __nv_bfloat16 g_W2T_hi[NB * KCB * C];  // [b][k][c]
__device__ __align__(16) __nv_bfloat16 g_W2T_lo[NB * KCB * C];
__device__ __align__(16) __nv_bfloat16 g_mb2_hi[C * KCB];       // [o][k]
__device__ __align__(16) __nv_bfloat16 g_mb2_lo[C * KCB];

#define SCALE_L2E 0.18033688011112042f   // 0.125 * log2(e)

// ---------------- helpers ----------------
__device__ __forceinline__ uint32_t smem_u32(const void* p) {
    uint32_t a;
    asm("{ .reg .u64 t; cvta.to.shared.u64 t, %1; cvt.u32.u64 %0, t; }" : "=r"(a) : "l"(p));
    return a;
}
__device__ __forceinline__ void mma16816(float* c,
        uint32_t a0, uint32_t a1, uint32_t a2, uint32_t a3,
        uint32_t b0, uint32_t b1) {
    asm volatile(
        "mma.sync.aligned.m16n8k16.row.col.f32.bf16.bf16.f32 "
        "{%0,%1,%2,%3}, {%4,%5,%6,%7}, {%8,%9}, {%0,%1,%2,%3};"
        : "+f"(c[0]), "+f"(c[1]), "+f"(c[2]), "+f"(c[3])
        : "r"(a0), "r"(a1), "r"(a2), "r"(a3), "r"(b0), "r"(b1));
}
#define LDSM4(r, addr) \
    asm volatile("ldmatrix.sync.aligned.m8n8.x4.shared.b16 {%0,%1,%2,%3}, [%4];" \
        : "=r"((r)[0]), "=r"((r)[1]), "=r"((r)[2]), "=r"((r)[3]) : "r"(addr))
__device__ __forceinline__ float ex2f(float x) {
    float r;
    asm("ex2.approx.ftz.f32 %0, %1;" : "=f"(r) : "f"(x));
    return r;
}
__device__ __forceinline__ uint32_t pack2(float a, float b) {
    __nv_bfloat162 h = __floats2bfloat162_rn(a, b);
    return *reinterpret_cast<uint32_t*>(&h);
}

// ---------------- K1: GroupNorm stats ----------------
__global__ void gn_stats_kernel(const float* __restrict__ x) {
    int bg = blockIdx.x;
    const float4* p = (const float4*)(x + (size_t)bg * (2 * HW));
    float s = 0.f, ss = 0.f;
    #pragma unroll 4
    for (int i = threadIdx.x; i < (2 * HW) / 4; i += blockDim.x) {
        float4 v = p[i];
        s  += (v.x + v.y) + (v.z + v.w);
        ss += (v.x * v.x + v.y * v.y) + (v.z * v.z + v.w * v.w);
    }
    #pragma unroll
    for (int o = 16; o; o >>= 1) {
        s  += __shfl_xor_sync(0xFFFFFFFFu, s, o);
        ss += __shfl_xor_sync(0xFFFFFFFFu, ss, o);
    }
    __shared__ float sm1[8], sm2[8];
    int w = threadIdx.x >> 5;
    if ((threadIdx.x & 31) == 0) { sm1[w] = s; sm2[w] = ss; }
    __syncthreads();
    if (threadIdx.x == 0) {
        float ts = 0.f, tss = 0.f;
        #pragma unroll
        for (int i = 0; i < 8; i++) { ts += sm1[i]; tss += sm2[i]; }
        const float inv = 1.f / (float)(2 * HW);
        float mean = ts * inv;
        float var  = tss * inv - mean * mean;
        g_mean[bg] = mean;
        g_rstd[bg] = rsqrtf(var + 1e-6f);
    }
}

// ---------------- K2: GN fold + folded phi bias ----------------
__global__ void prep0_kernel(const float* __restrict__ phi_w, const float* __restrict__ phi_b,
                             const float* __restrict__ gn_w, const float* __restrict__ gn_b) {
    int b = blockIdx.x, c = threadIdx.x;
    __shared__ float shB[C];
    int g = c >> 1;
    float a = g_rstd[b * NG + g] * gn_w[c];
    g_scA[b * C + c] = a;
    shB[c] = gn_b[c] - g_mean[b * NG + g] * a;
    __syncthreads();
    float acc = phi_b[c];
    #pragma unroll
    for (int j = 0; j < C; j++) acc += phi_w[c * C + j] * shB[j];
    g_bias2[b * C + c] = acc;
}

// ---------------- K3: G[k][c] = 0.125*log2e * (phi^T @ mb)  (batch-independent) ---
__global__ void prepG_kernel(const float* __restrict__ phi_w, const float* __restrict__ mb) {
    int k = blockIdx.x, c = threadIdx.x;
    float a0 = 0.f, a1 = 0.f, a2 = 0.f, a3 = 0.f;
    #pragma unroll
    for (int o = 0; o < C; o += 4) {
        a0 += phi_w[(o + 0) * C + c] * mb[(o + 0) * KCB + k];
        a1 += phi_w[(o + 1) * C + c] * mb[(o + 1) * KCB + k];
        a2 += phi_w[(o + 2) * C + c] * mb[(o + 2) * KCB + k];
        a3 += phi_w[(o + 3) * C + c] * mb[(o + 3) * KCB + k];
    }
    g_G[k * C + c] = SCALE_L2E * ((a0 + a1) + (a2 + a3));
}

// ---------------- K4: per-batch scale/split of G + sbias ----------------
__global__ void prep_scale_kernel(const float* __restrict__ mb) {
    int k = blockIdx.x, b = blockIdx.y, c = threadIdx.x;
    float v = g_scA[b * C + c] * g_G[k * C + c];
    __nv_bfloat16 hi = __float2bfloat16(v);
    __nv_bfloat16 lo = __float2bfloat16(v - __bfloat162float(hi));
    g_W2T_hi[b * (KCB * C) + k * C + c] = hi;
    g_W2T_lo[b * (KCB * C) + k * C + c] = lo;

    float p = g_bias2[b * C + c] * mb[c * KCB + k];
    #pragma unroll
    for (int o = 16; o; o >>= 1) p += __shfl_xor_sync(0xFFFFFFFFu, p, o);
    __shared__ float ws[2];
    if ((c & 31) == 0) ws[c >> 5] = p;
    __syncthreads();
    if (c == 0) g_sbias[b * KCB + k] = SCALE_L2E * (ws[0] + ws[1]);
}

// ---------------- K5: mb2[o][k] = wz_w @ mb split planes ----------------
__global__ void prep2_kernel(const float* __restrict__ wz_w, const float* __restrict__ mb) {
    int k = blockIdx.x, o = threadIdx.x;
    float a0 = 0.f, a1 = 0.f, a2 = 0.f, a3 = 0.f;
    #pragma unroll
    for (int c = 0; c < C; c += 4) {
        a0 += wz_w[o * C + c + 0] * mb[(c + 0) * KCB + k];
        a1 += wz_w[o * C + c + 1] * mb[(c + 1) * KCB + k];
        a2 += wz_w[o * C + c + 2] * mb[(c + 2) * KCB + k];
        a3 += wz_w[o * C + c + 3] * mb[(c + 3) * KCB + k];
    }
    float acc = (a0 + a1) + (a2 + a3);
    __nv_bfloat16 hi = __float2bfloat16(acc);
    __nv_bfloat16 lo = __float2bfloat16(acc - __bfloat162float(hi));
    g_mb2_hi[o * KCB + k] = hi;
    g_mb2_lo[o * KCB + k] = lo;
}

// ---------------- weight chunk prefetch via cp.async ----------------
__device__ __forceinline__ void prefetch_chunk(int ci, int st, int b, int tid, uint32_t smb) {
    #pragma unroll
    for (int t = 0; t < 8; t++) {
        int idx = tid + t * 256;
        int plane = idx >> 9, rem = idx & 511, row = rem >> 3, seg = rem & 7;
        const __nv_bfloat16* src;
        if      (plane == 0) src = g_W2T_hi + b * (KCB * C) + (ci * 64 + row) * 64 + seg * 8;
        else if (plane == 1) src = g_W2T_lo + b * (KCB * C) + (ci * 64 + row) * 64 + seg * 8;
        else if (plane == 2) src = g_mb2_hi + row * KCB + ci * 64 + seg * 8;
        else                 src = g_mb2_lo + row * KCB + ci * 64 + seg * 8;
        uint32_t dst = smb + WB_OFF + st * 36864 + plane * 9216 + row * 144 + seg * 16;
        asm volatile("cp.async.ca.shared.global [%0], [%1], 16;" :: "r"(dst), "l"(src) : "memory");
    }
}

// ---------------- K6: main fused kernel ----------------
__global__ __launch_bounds__(THREADS, 1)
void fused_main_kernel(const float* __restrict__ x, float* __restrict__ out,
                       const float* __restrict__ wz_b) {
    extern __shared__ char S[];
    const int tid = threadIdx.x, wid = tid >> 5, lane = tid & 31;
    const int g = lane >> 2, tq = lane & 3;
    const int b = blockIdx.y;
    const int tok0 = blockIdx.x * TOKT;
    const int wtok = wid * 32;
    const uint32_t smb = smem_u32(S);

    prefetch_chunk(0, 0, b, tid, smb);
    asm volatile("cp.async.commit_group;" ::: "memory");
    prefetch_chunk(1, 1, b, tid, smb);
    asm volatile("cp.async.commit_group;" ::: "memory");

    if (tid < C) ((float*)(S + WZB_OFF))[tid] = wz_b[tid];
    for (int i = tid; i < KCB; i += THREADS)
        ((float*)(S + SB_OFF))[i] = g_sbias[b * KCB + i];

    // X tile: global [c][t] -> smem split hi/lo [t][c], rows padded to 72 bf16
    const float* xg = x + (size_t)b * C * HW + tok0;
    {
        __nv_bfloat16* XHp = (__nv_bfloat16*)(S + XH_OFF);
        __nv_bfloat16* XLp = (__nv_bfloat16*)(S + XL_OFF);
        #pragma unroll
        for (int it = 0; it < 16; it++) {
            int i = tid + it * 256;
            int c = i >> 6, t64 = i & 63;
            float4 v = *(const float4*)(xg + (size_t)c * HW + t64 * 4);
            float vv[4] = {v.x, v.y, v.z, v.w};
            #pragma unroll
            for (int j = 0; j < 4; j++) {
                int tk = t64 * 4 + j;
                __nv_bfloat16 h = __float2bfloat16(vv[j]);
                XHp[tk * 72 + c] = h;
                XLp[tk * 72 + c] = __float2bfloat16(vv[j] - __bfloat162float(h));
            }
        }
    }
    __syncthreads();

    // A fragments via ldmatrix.x4 (held for all chunks)
    uint32_t ah[2][4][4], al[2][4][4];
    {
        uint32_t rowsel = (uint32_t)(lane & 15);
        uint32_t colsel = (uint32_t)((lane >> 4) * 16);
        #pragma unroll
        for (int mt = 0; mt < 2; mt++) {
            uint32_t rbase = (uint32_t)(wtok + mt * 16) + rowsel;
            #pragma unroll
            for (int kt = 0; kt < 4; kt++) {
                uint32_t off = rbase * 144 + (uint32_t)kt * 32 + colsel;
                LDSM4(ah[mt][kt], smb + XH_OFF + off);
                LDSM4(al[mt][kt], smb + XL_OFF + off);
            }
        }
    }

    float yacc[2][8][4];
    #pragma unroll
    for (int mt = 0; mt < 2; mt++)
        #pragma unroll
        for (int nt = 0; nt < 8; nt++)
            #pragma unroll
            for (int q = 0; q < 4; q++) yacc[mt][nt][q] = 0.f;
    float zacc[4] = {0.f, 0.f, 0.f, 0.f};

    const uint32_t brow = (uint32_t)(lane & 7) * 144 + (uint32_t)((lane >> 3) * 16);

    for (int ci = 0; ci < 8; ci++) {
        if (ci < 7) asm volatile("cp.async.wait_group 1;" ::: "memory");
        else        asm volatile("cp.async.wait_group 0;" ::: "memory");
        __syncthreads();

        const uint32_t stg = smb + WB_OFF + (uint32_t)((ci & 1) * 36864);
        const uint32_t Wh = stg, Wl = stg + 9216, Mh = stg + 18432, Ml = stg + 27648;
        const float* sbp = (const float*)(S + SB_OFF) + ci * 64;

        #pragma unroll
        for (int mt = 0; mt < 2; mt++) {
            // ---- GEMM2: scores [16 x 64], 3 split products ----
            float sc[8][4];
            #pragma unroll
            for (int nt = 0; nt < 8; nt++)
                #pragma unroll
                for (int q = 0; q < 4; q++) sc[nt][q] = 0.f;

            #pragma unroll
            for (int nt = 0; nt < 8; nt++) {
                uint32_t radr = (uint32_t)(nt * 8) * 144 + brow;
                uint32_t bh[8], bl[8];
                LDSM4(bh,     Wh + radr);
                LDSM4(bh + 4, Wh + radr + 64);
                LDSM4(bl,     Wl + radr);
                LDSM4(bl + 4, Wl + radr + 64);
                #pragma unroll
                for (int kt = 0; kt < 4; kt++) {
                    mma16816(sc[nt], ah[mt][kt][0], ah[mt][kt][1], ah[mt][kt][2], ah[mt][kt][3], bh[2 * kt], bh[2 * kt + 1]);
                    mma16816(sc[nt], al[mt][kt][0], al[mt][kt][1], al[mt][kt][2], al[mt][kt][3], bh[2 * kt], bh[2 * kt + 1]);
                    mma16816(sc[nt], ah[mt][kt][0], ah[mt][kt][1], ah[mt][kt][2], ah[mt][kt][3], bl[2 * kt], bl[2 * kt + 1]);
                }
            }

            // ---- exp via ex2 (log2e pre-folded) + zsum + split to A-frags ----
            uint32_t eh[8], eh2[8], el[8], el2[8];
            #pragma unroll
            for (int nt = 0; nt < 8; nt++) {
                float sbx = sbp[nt * 8 + 2 * tq];
                float sby = sbp[nt * 8 + 2 * tq + 1];
                float e0 = ex2f(sc[nt][0] + sbx);
                float e1 = ex2f(sc[nt][1] + sby);
                float e2 = ex2f(sc[nt][2] + sbx);
                float e3 = ex2f(sc[nt][3] + sby);
                zacc[mt * 2 + 0] += e0 + e1;
                zacc[mt * 2 + 1] += e2 + e3;
                __nv_bfloat162 h01 = __floats2bfloat162_rn(e0, e1);
                __nv_bfloat162 h23 = __floats2bfloat162_rn(e2, e3);
                eh[nt]  = *reinterpret_cast<uint32_t*>(&h01);
                eh2[nt] = *reinterpret_cast<uint32_t*>(&h23);
                el[nt]  = pack2(e0 - __low2float(h01), e1 - __high2float(h01));
                el2[nt] = pack2(e2 - __low2float(h23), e3 - __high2float(h23));
            }

            // ---- GEMM3: y += E @ mb2^T, 3 split products ----
            #pragma unroll
            for (int nt = 0; nt < 8; nt++) {
                uint32_t radr = (uint32_t)(nt * 8) * 144 + brow;
                uint32_t mh[8], ml[8];
                LDSM4(mh,     Mh + radr);
                LDSM4(mh + 4, Mh + radr + 64);
                LDSM4(ml,     Ml + radr);
                LDSM4(ml + 4, Ml + radr + 64);
                #pragma unroll
                for (int kt = 0; kt < 4; kt++) {
                    uint32_t a0 = eh[2 * kt],      a1 = eh2[2 * kt];
                    uint32_t a2 = eh[2 * kt + 1],  a3 = eh2[2 * kt + 1];
                    uint32_t l0 = el[2 * kt],      l1 = el2[2 * kt];
                    uint32_t l2 = el[2 * kt + 1],  l3 = el2[2 * kt + 1];
                    mma16816(yacc[mt][nt], a0, a1, a2, a3, mh[2 * kt], mh[2 * kt + 1]);
                    mma16816(yacc[mt][nt], l0, l1, l2, l3, mh[2 * kt], mh[2 * kt + 1]);
                    mma16816(yacc[mt][nt], a0, a1, a2, a3, ml[2 * kt], ml[2 * kt + 1]);
                }
            }
        }

        __syncthreads();
        if (ci + 2 < 8) {
            prefetch_chunk(ci + 2, ci & 1, b, tid, smb);
            asm volatile("cp.async.commit_group;" ::: "memory");
        }
    }

    // row-sum Z over quad lanes
    #pragma unroll
    for (int q = 0; q < 4; q++) {
        zacc[q] += __shfl_xor_sync(0xFFFFFFFFu, zacc[q], 1);
        zacc[q] += __shfl_xor_sync(0xFFFFFFFFu, zacc[q], 2);
    }
    float* ZRp = (float*)(S + ZR_OFF);
    if (tq == 0) {
        #pragma unroll
        for (int mt = 0; mt < 2; mt++) {
            ZRp[wtok + mt * 16 + g]     = zacc[mt * 2 + 0];
            ZRp[wtok + mt * 16 + 8 + g] = zacc[mt * 2 + 1];
        }
    }
    __syncwarp();
    float iz[4];
    #pragma unroll
    for (int mt = 0; mt < 2; mt++) {
        iz[mt * 2 + 0] = 1.f / ZRp[wtok + mt * 16 + g];
        iz[mt * 2 + 1] = 1.f / ZRp[wtok + mt * 16 + 8 + g];
    }

    // stage y to smem [o][tok] (pad 260) for coalesced output
    float* YS = (float*)S;
    __syncthreads();
    #pragma unroll
    for (int mt = 0; mt < 2; mt++) {
        int r0 = wtok + mt * 16 + g;
        #pragma unroll
        for (int nt = 0; nt < 8; nt++) {
            int o0 = nt * 8 + 2 * tq;
            YS[o0 * 260 + r0]           = yacc[mt][nt][0] * iz[mt * 2];
            YS[(o0 + 1) * 260 + r0]     = yacc[mt][nt][1] * iz[mt * 2];
            YS[o0 * 260 + r0 + 8]       = yacc[mt][nt][2] * iz[mt * 2 + 1];
            YS[(o0 + 1) * 260 + r0 + 8] = yacc[mt][nt][3] * iz[mt * 2 + 1];
        }
    }
    __syncthreads();

    // out = y + wz_b + residual, coalesced float4
    const float* wzp = (const float*)(S + WZB_OFF);
    float* og = out + (size_t)b * C * HW + tok0;
    #pragma unroll
    for (int it = 0; it < 16; it++) {
        int i = tid + it * 256;
        int o = i >> 6, t64 = i & 63;
        float4 ys = *(const float4*)(YS + o * 260 + t64 * 4);
        float4 xr = *(const float4*)(xg + (size_t)o * HW + t64 * 4);
        float wb = wzp[o];
        float4 r;
        r.x = ys.x + xr.x + wb;
        r.y = ys.y + xr.y + wb;
        r.z = ys.z + xr.z + wb;
        r.w = ys.w + xr.w + wb;
        *(float4*)(og + (size_t)o * HW + t64 * 4) = r;
    }
}

// ---------------------------------------------------------------------------
extern "C" void kernel_launch(void* const* d_in, const int* in_sizes, int n_in,
                              void* d_out, int out_size) {
    const float* x     = (const float*)d_in[0];
    const float* mb    = (const float*)d_in[1];
    const float* phi_w = (const float*)d_in[2];
    const float* phi_b = (const float*)d_in[3];
    const float* gn_w  = (const float*)d_in[4];
    const float* gn_b  = (const float*)d_in[5];
    const float* wz_w  = (const float*)d_in[6];
    const float* wz_b  = (const float*)d_in[7];
    float* out = (float*)d_out;

    cudaFuncSetAttribute(fused_main_kernel,
                         cudaFuncAttributeMaxDynamicSharedMemorySize, SMEM_TOTAL);

    gn_stats_kernel<<<NB * NG, 256>>>(x);
    prep0_kernel<<<NB, C>>>(phi_w, phi_b, gn_w, gn_b);
    prepG_kernel<<<KCB, C>>>(phi_w, mb);
    {
        dim3 gs(KCB, NB);
        prep_scale_kernel<<<gs, C>>>(mb);
    }
    prep2_kernel<<<KCB, C>>>(wz_w, mb);

    dim3 grid(HW / TOKT, NB);
    fused_main_kernel<<<grid, THREADS, SMEM_TOTAL>>>(x, out, wz_b);
}

// round 6
// speedup vs baseline: 1.3359x; 1.3359x over previous
#include <cuda_runtime.h>
#include <cuda_bf16.h>
#include <cstdint>

#define NB   10
#define C    64
#define HW   16384
#define KCB  512
#define NG   32
#define TOKT 128
#define THREADS 256

// ---- smem layout (bytes from dynamic base) ----
// X rows padded to 144B (72 bf16) for conflict-free ldmatrix
#define XH_OFF   0                // 128 x 144B = 18432
#define XL_OFF   18432
#define WB_OFF   36864            // 2 stages x (4 planes x 9216B) = 73728
#define SB_OFF   110592           // sbias 512 f32
#define ZR_OFF   112640           // zrow 128 f32
#define WZB_OFF  113152           // wz_b 64 f32
#define SMEM_TOTAL 113408
// epilogue y-stage reuses [0 .. 33792): 64 rows x 132 f32

// ---------------- device-global scratch ----------------
__device__ float g_mean[NB * NG], g_rstd[NB * NG];
__device__ float g_scA[NB * C], g_bias2[NB * C];
__device__ float g_G[KCB * C];                                  // [k][c], incl 0.125*log2e
__device__ float g_sbias[NB * KCB];                             // incl 0.125*log2e
__device__ __align__(16) __nv_bfloat16 g_W2T_hi[NB * KCB * C];  // [b][k][c]
__device__ __align__(16) __nv_bfloat16 g_W2T_lo[NB * KCB * C];
__device__ __align__(16) __nv_bfloat16 g_mb2_hi[C * KCB];       // [o][k]
__device__ __align__(16) __nv_bfloat16 g_mb2_lo[C * KCB];

#define SCALE_L2E 0.18033688011112042f   // 0.125 * log2(e)

// ---------------- helpers ----------------
__device__ __forceinline__ uint32_t smem_u32(const void* p) {
    uint32_t a;
    asm("{ .reg .u64 t; cvta.to.shared.u64 t, %1; cvt.u32.u64 %0, t; }" : "=r"(a) : "l"(p));
    return a;
}
__device__ __forceinline__ void mma16816(float* c,
        uint32_t a0, uint32_t a1, uint32_t a2, uint32_t a3,
        uint32_t b0, uint32_t b1) {
    asm volatile(
        "mma.sync.aligned.m16n8k16.row.col.f32.bf16.bf16.f32 "
        "{%0,%1,%2,%3}, {%4,%5,%6,%7}, {%8,%9}, {%0,%1,%2,%3};"
        : "+f"(c[0]), "+f"(c[1]), "+f"(c[2]), "+f"(c[3])
        : "r"(a0), "r"(a1), "r"(a2), "r"(a3), "r"(b0), "r"(b1));
}
#define LDSM4(r, addr) \
    asm volatile("ldmatrix.sync.aligned.m8n8.x4.shared.b16 {%0,%1,%2,%3}, [%4];" \
        : "=r"((r)[0]), "=r"((r)[1]), "=r"((r)[2]), "=r"((r)[3]) : "r"(addr))
__device__ __forceinline__ float ex2f(float x) {
    float r;
    asm("ex2.approx.ftz.f32 %0, %1;" : "=f"(r) : "f"(x));
    return r;
}
__device__ __forceinline__ uint32_t pack2(float a, float b) {
    __nv_bfloat162 h = __floats2bfloat162_rn(a, b);
    return *reinterpret_cast<uint32_t*>(&h);
}

// ---------------- K1: GroupNorm stats ----------------
__global__ void gn_stats_kernel(const float* __restrict__ x) {
    int bg = blockIdx.x;
    const float4* p = (const float4*)(x + (size_t)bg * (2 * HW));
    float s = 0.f, ss = 0.f;
    #pragma unroll 4
    for (int i = threadIdx.x; i < (2 * HW) / 4; i += blockDim.x) {
        float4 v = p[i];
        s  += (v.x + v.y) + (v.z + v.w);
        ss += (v.x * v.x + v.y * v.y) + (v.z * v.z + v.w * v.w);
    }
    #pragma unroll
    for (int o = 16; o; o >>= 1) {
        s  += __shfl_xor_sync(0xFFFFFFFFu, s, o);
        ss += __shfl_xor_sync(0xFFFFFFFFu, ss, o);
    }
    __shared__ float sm1[8], sm2[8];
    int w = threadIdx.x >> 5;
    if ((threadIdx.x & 31) == 0) { sm1[w] = s; sm2[w] = ss; }
    __syncthreads();
    if (threadIdx.x == 0) {
        float ts = 0.f, tss = 0.f;
        #pragma unroll
        for (int i = 0; i < 8; i++) { ts += sm1[i]; tss += sm2[i]; }
        const float inv = 1.f / (float)(2 * HW);
        float mean = ts * inv;
        float var  = tss * inv - mean * mean;
        g_mean[bg] = mean;
        g_rstd[bg] = rsqrtf(var + 1e-6f);
    }
}

// ---------------- K2: GN fold + folded phi bias ----------------
__global__ void prep0_kernel(const float* __restrict__ phi_w, const float* __restrict__ phi_b,
                             const float* __restrict__ gn_w, const float* __restrict__ gn_b) {
    int b = blockIdx.x, c = threadIdx.x;
    __shared__ float shB[C];
    int g = c >> 1;
    float a = g_rstd[b * NG + g] * gn_w[c];
    g_scA[b * C + c] = a;
    shB[c] = gn_b[c] - g_mean[b * NG + g] * a;
    __syncthreads();
    float acc = phi_b[c];
    #pragma unroll
    for (int j = 0; j < C; j++) acc += phi_w[c * C + j] * shB[j];
    g_bias2[b * C + c] = acc;
}

// ---------------- K3: G[k][c] = 0.125*log2e * (phi^T @ mb) ----------------
__global__ void prepG_kernel(const float* __restrict__ phi_w, const float* __restrict__ mb) {
    int k = blockIdx.x, c = threadIdx.x;
    float a0 = 0.f, a1 = 0.f, a2 = 0.f, a3 = 0.f;
    #pragma unroll
    for (int o = 0; o < C; o += 4) {
        a0 += phi_w[(o + 0) * C + c] * mb[(o + 0) * KCB + k];
        a1 += phi_w[(o + 1) * C + c] * mb[(o + 1) * KCB + k];
        a2 += phi_w[(o + 2) * C + c] * mb[(o + 2) * KCB + k];
        a3 += phi_w[(o + 3) * C + c] * mb[(o + 3) * KCB + k];
    }
    g_G[k * C + c] = SCALE_L2E * ((a0 + a1) + (a2 + a3));
}

// ---------------- K4: per-batch scale/split of G + sbias ----------------
__global__ void prep_scale_kernel(const float* __restrict__ mb) {
    int k = blockIdx.x, b = blockIdx.y, c = threadIdx.x;
    float v = g_scA[b * C + c] * g_G[k * C + c];
    __nv_bfloat16 hi = __float2bfloat16(v);
    __nv_bfloat16 lo = __float2bfloat16(v - __bfloat162float(hi));
    g_W2T_hi[b * (KCB * C) + k * C + c] = hi;
    g_W2T_lo[b * (KCB * C) + k * C + c] = lo;

    float p = g_bias2[b * C + c] * mb[c * KCB + k];
    #pragma unroll
    for (int o = 16; o; o >>= 1) p += __shfl_xor_sync(0xFFFFFFFFu, p, o);
    __shared__ float ws[2];
    if ((c & 31) == 0) ws[c >> 5] = p;
    __syncthreads();
    if (c == 0) g_sbias[b * KCB + k] = SCALE_L2E * (ws[0] + ws[1]);
}

// ---------------- K5: mb2[o][k] = wz_w @ mb split planes ----------------
__global__ void prep2_kernel(const float* __restrict__ wz_w, const float* __restrict__ mb) {
    int k = blockIdx.x, o = threadIdx.x;
    float a0 = 0.f, a1 = 0.f, a2 = 0.f, a3 = 0.f;
    #pragma unroll
    for (int c = 0; c < C; c += 4) {
        a0 += wz_w[o * C + c + 0] * mb[(c + 0) * KCB + k];
        a1 += wz_w[o * C + c + 1] * mb[(c + 1) * KCB + k];
        a2 += wz_w[o * C + c + 2] * mb[(c + 2) * KCB + k];
        a3 += wz_w[o * C + c + 3] * mb[(c + 3) * KCB + k];
    }
    float acc = (a0 + a1) + (a2 + a3);
    __nv_bfloat16 hi = __float2bfloat16(acc);
    __nv_bfloat16 lo = __float2bfloat16(acc - __bfloat162float(hi));
    g_mb2_hi[o * KCB + k] = hi;
    g_mb2_lo[o * KCB + k] = lo;
}

// ---------------- weight chunk prefetch via cp.async ----------------
__device__ __forceinline__ void prefetch_chunk(int ci, int st, int b, int tid, uint32_t smb) {
    #pragma unroll
    for (int t = 0; t < 8; t++) {
        int idx = tid + t * 256;
        int plane = idx >> 9, rem = idx & 511, row = rem >> 3, seg = rem & 7;
        const __nv_bfloat16* src;
        if      (plane == 0) src = g_W2T_hi + b * (KCB * C) + (ci * 64 + row) * 64 + seg * 8;
        else if (plane == 1) src = g_W2T_lo + b * (KCB * C) + (ci * 64 + row) * 64 + seg * 8;
        else if (plane == 2) src = g_mb2_hi + row * KCB + ci * 64 + seg * 8;
        else                 src = g_mb2_lo + row * KCB + ci * 64 + seg * 8;
        uint32_t dst = smb + WB_OFF + st * 36864 + plane * 9216 + row * 144 + seg * 16;
        asm volatile("cp.async.ca.shared.global [%0], [%1], 16;" :: "r"(dst), "l"(src) : "memory");
    }
}

// ---------------- K6: main fused kernel (16 tokens per warp) ----------------
__global__ __launch_bounds__(THREADS, 1)
void fused_main_kernel(const float* __restrict__ x, float* __restrict__ out,
                       const float* __restrict__ wz_b) {
    extern __shared__ char S[];
    const int tid = threadIdx.x, wid = tid >> 5, lane = tid & 31;
    const int g = lane >> 2, tq = lane & 3;
    const int b = blockIdx.y;
    const int tok0 = blockIdx.x * TOKT;
    const int wtok = wid * 16;
    const uint32_t smb = smem_u32(S);

    prefetch_chunk(0, 0, b, tid, smb);
    asm volatile("cp.async.commit_group;" ::: "memory");
    prefetch_chunk(1, 1, b, tid, smb);
    asm volatile("cp.async.commit_group;" ::: "memory");

    if (tid < C) ((float*)(S + WZB_OFF))[tid] = wz_b[tid];
    for (int i = tid; i < KCB; i += THREADS)
        ((float*)(S + SB_OFF))[i] = g_sbias[b * KCB + i];

    // X tile: global [c][t] -> smem split hi/lo [t][c], rows padded to 72 bf16
    const float* xg = x + (size_t)b * C * HW + tok0;
    {
        __nv_bfloat16* XHp = (__nv_bfloat16*)(S + XH_OFF);
        __nv_bfloat16* XLp = (__nv_bfloat16*)(S + XL_OFF);
        #pragma unroll
        for (int it = 0; it < 8; it++) {
            int i = tid + it * 256;
            int c = i >> 5, t32 = i & 31;
            float4 v = *(const float4*)(xg + (size_t)c * HW + t32 * 4);
            float vv[4] = {v.x, v.y, v.z, v.w};
            #pragma unroll
            for (int j = 0; j < 4; j++) {
                int tk = t32 * 4 + j;
                __nv_bfloat16 h = __float2bfloat16(vv[j]);
                XHp[tk * 72 + c] = h;
                XLp[tk * 72 + c] = __float2bfloat16(vv[j] - __bfloat162float(h));
            }
        }
    }
    __syncthreads();

    // A fragments via ldmatrix.x4 (held for all chunks): 16 rows x 64 cols
    uint32_t ah[4][4], al[4][4];
    {
        uint32_t rowsel = (uint32_t)(lane & 15);
        uint32_t colsel = (uint32_t)((lane >> 4) * 16);
        uint32_t rbase = (uint32_t)wtok + rowsel;
        #pragma unroll
        for (int kt = 0; kt < 4; kt++) {
            uint32_t off = rbase * 144 + (uint32_t)kt * 32 + colsel;
            LDSM4(ah[kt], smb + XH_OFF + off);
            LDSM4(al[kt], smb + XL_OFF + off);
        }
    }

    float yacc[8][4];
    #pragma unroll
    for (int nt = 0; nt < 8; nt++)
        #pragma unroll
        for (int q = 0; q < 4; q++) yacc[nt][q] = 0.f;
    float zacc[2] = {0.f, 0.f};

    const uint32_t brow = (uint32_t)(lane & 7) * 144 + (uint32_t)((lane >> 3) * 16);

    for (int ci = 0; ci < 8; ci++) {
        if (ci < 7) asm volatile("cp.async.wait_group 1;" ::: "memory");
        else        asm volatile("cp.async.wait_group 0;" ::: "memory");
        __syncthreads();

        const uint32_t stg = smb + WB_OFF + (uint32_t)((ci & 1) * 36864);
        const uint32_t Wh = stg, Wl = stg + 9216, Mh = stg + 18432, Ml = stg + 27648;
        const float* sbp = (const float*)(S + SB_OFF) + ci * 64;

        // ---- GEMM2: scores [16 x 64], 3 split products ----
        float sc[8][4];
        #pragma unroll
        for (int nt = 0; nt < 8; nt++)
            #pragma unroll
            for (int q = 0; q < 4; q++) sc[nt][q] = 0.f;

        #pragma unroll
        for (int nt = 0; nt < 8; nt++) {
            uint32_t radr = (uint32_t)(nt * 8) * 144 + brow;
            uint32_t bh[8], bl[8];
            LDSM4(bh,     Wh + radr);
            LDSM4(bh + 4, Wh + radr + 64);
            LDSM4(bl,     Wl + radr);
            LDSM4(bl + 4, Wl + radr + 64);
            #pragma unroll
            for (int kt = 0; kt < 4; kt++) {
                mma16816(sc[nt], ah[kt][0], ah[kt][1], ah[kt][2], ah[kt][3], bh[2 * kt], bh[2 * kt + 1]);
                mma16816(sc[nt], al[kt][0], al[kt][1], al[kt][2], al[kt][3], bh[2 * kt], bh[2 * kt + 1]);
                mma16816(sc[nt], ah[kt][0], ah[kt][1], ah[kt][2], ah[kt][3], bl[2 * kt], bl[2 * kt + 1]);
            }
        }

        // ---- exp via ex2 (log2e pre-folded) + zsum + split to A-frags ----
        uint32_t eh[8], eh2[8], el[8], el2[8];
        #pragma unroll
        for (int nt = 0; nt < 8; nt++) {
            float sbx = sbp[nt * 8 + 2 * tq];
            float sby = sbp[nt * 8 + 2 * tq + 1];
            float e0 = ex2f(sc[nt][0] + sbx);
            float e1 = ex2f(sc[nt][1] + sby);
            float e2 = ex2f(sc[nt][2] + sbx);
            float e3 = ex2f(sc[nt][3] + sby);
            zacc[0] += e0 + e1;
            zacc[1] += e2 + e3;
            __nv_bfloat162 h01 = __floats2bfloat162_rn(e0, e1);
            __nv_bfloat162 h23 = __floats2bfloat162_rn(e2, e3);
            eh[nt]  = *reinterpret_cast<uint32_t*>(&h01);
            eh2[nt] = *reinterpret_cast<uint32_t*>(&h23);
            el[nt]  = pack2(e0 - __low2float(h01), e1 - __high2float(h01));
            el2[nt] = pack2(e2 - __low2float(h23), e3 - __high2float(h23));
        }

        // ---- GEMM3: y += E @ mb2^T, 3 split products ----
        #pragma unroll
        for (int nt = 0; nt < 8; nt++) {
            uint32_t radr = (uint32_t)(nt * 8) * 144 + brow;
            uint32_t mh[8], ml[8];
            LDSM4(mh,     Mh + radr);
            LDSM4(mh + 4, Mh + radr + 64);
            LDSM4(ml,     Ml + radr);
            LDSM4(ml + 4, Ml + radr + 64);
            #pragma unroll
            for (int kt = 0; kt < 4; kt++) {
                uint32_t a0 = eh[2 * kt],      a1 = eh2[2 * kt];
                uint32_t a2 = eh[2 * kt + 1],  a3 = eh2[2 * kt + 1];
                uint32_t l0 = el[2 * kt],      l1 = el2[2 * kt];
                uint32_t l2 = el[2 * kt + 1],  l3 = el2[2 * kt + 1];
                mma16816(yacc[nt], a0, a1, a2, a3, mh[2 * kt], mh[2 * kt + 1]);
                mma16816(yacc[nt], l0, l1, l2, l3, mh[2 * kt], mh[2 * kt + 1]);
                mma16816(yacc[nt], a0, a1, a2, a3, ml[2 * kt], ml[2 * kt + 1]);
            }
        }

        __syncthreads();
        if (ci + 2 < 8) {
            prefetch_chunk(ci + 2, ci & 1, b, tid, smb);
            asm volatile("cp.async.commit_group;" ::: "memory");
        }
    }

    // row-sum Z over quad lanes
    #pragma unroll
    for (int q = 0; q < 2; q++) {
        zacc[q] += __shfl_xor_sync(0xFFFFFFFFu, zacc[q], 1);
        zacc[q] += __shfl_xor_sync(0xFFFFFFFFu, zacc[q], 2);
    }
    float* ZRp = (float*)(S + ZR_OFF);
    if (tq == 0) {
        ZRp[wtok + g]     = zacc[0];
        ZRp[wtok + 8 + g] = zacc[1];
    }
    __syncwarp();
    float iz0 = 1.f / ZRp[wtok + g];
    float iz1 = 1.f / ZRp[wtok + 8 + g];

    // stage y to smem [o][tok] (pad 132) for coalesced output
    float* YS = (float*)S;
    __syncthreads();
    {
        int r0 = wtok + g;
        #pragma unroll
        for (int nt = 0; nt < 8; nt++) {
            int o0 = nt * 8 + 2 * tq;
            YS[o0 * 132 + r0]           = yacc[nt][0] * iz0;
            YS[(o0 + 1) * 132 + r0]     = yacc[nt][1] * iz0;
            YS[o0 * 132 + r0 + 8]       = yacc[nt][2] * iz1;
            YS[(o0 + 1) * 132 + r0 + 8] = yacc[nt][3] * iz1;
        }
    }
    __syncthreads();

    // out = y + wz_b + residual, coalesced float4
    const float* wzp = (const float*)(S + WZB_OFF);
    float* og = out + (size_t)b * C * HW + tok0;
    #pragma unroll
    for (int it = 0; it < 8; it++) {
        int i = tid + it * 256;
        int o = i >> 5, t32 = i & 31;
        float4 ys = *(const float4*)(YS + o * 132 + t32 * 4);
        float4 xr = *(const float4*)(xg + (size_t)o * HW + t32 * 4);
        float wb = wzp[o];
        float4 r;
        r.x = ys.x + xr.x + wb;
        r.y = ys.y + xr.y + wb;
        r.z = ys.z + xr.z + wb;
        r.w = ys.w + xr.w + wb;
        *(float4*)(og + (size_t)o * HW + t32 * 4) = r;
    }
}

// ---------------------------------------------------------------------------
extern "C" void kernel_launch(void* const* d_in, const int* in_sizes, int n_in,
                              void* d_out, int out_size) {
    const float* x     = (const float*)d_in[0];
    const float* mb    = (const float*)d_in[1];
    const float* phi_w = (const float*)d_in[2];
    const float* phi_b = (const float*)d_in[3];
    const float* gn_w  = (const float*)d_in[4];
    const float* gn_b  = (const float*)d_in[5];
    const float* wz_w  = (const float*)d_in[6];
    const float* wz_b  = (const float*)d_in[7];
    float* out = (float*)d_out;

    cudaFuncSetAttribute(fused_main_kernel,
                         cudaFuncAttributeMaxDynamicSharedMemorySize, SMEM_TOTAL);

    gn_stats_kernel<<<NB * NG, 256>>>(x);
    prep0_kernel<<<NB, C>>>(phi_w, phi_b, gn_w, gn_b);
    prepG_kernel<<<KCB, C>>>(phi_w, mb);
    {
        dim3 gs(KCB, NB);
        prep_scale_kernel<<<gs, C>>>(mb);
    }
    prep2_kernel<<<KCB, C>>>(wz_w, mb);

    dim3 grid(HW / TOKT, NB);
    fused_main_kernel<<<grid, THREADS, SMEM_TOTAL>>>(x, out, wz_b);
}

// round 7
// speedup vs baseline: 1.6296x; 1.2199x over previous
#include <cuda_runtime.h>
#include <cuda_bf16.h>
#include <cstdint>

#define NB   10
#define C    64
#define HW   16384
#define KCB  512
#define NG   32
#define TOKT 128
#define THREADS 256

// ---- smem layout (bytes from dynamic base) ----
#define WB_OFF   0                // 2 stages x (4 planes x 9216B) = 73728
#define SB_OFF   73728            // sbias 512 f32 = 2048
#define ZR_OFF   75776            // zrow 128 f32 = 512
#define WZB_OFF  76288            // wz_b 64 f32 = 256
#define SMEM_TOTAL 76544
// epilogue y-stage reuses stage0 [0 .. 33792): 64 rows x 132 f32

// ---------------- device-global scratch ----------------
__device__ float g_mean[NB * NG], g_rstd[NB * NG];
__device__ float g_scA[NB * C], g_bias2[NB * C];
__device__ float g_G[KCB * C];                                  // [k][c], incl 0.125*log2e
__device__ float g_sbias[NB * KCB];                             // incl 0.125*log2e
__device__ __align__(16) __nv_bfloat16 g_W2T_hi[NB * KCB * C];  // [b][k][c]
__device__ __align__(16) __nv_bfloat16 g_W2T_lo[NB * KCB * C];
__device__ __align__(16) __nv_bfloat16 g_mb2_hi[C * KCB];       // [o][k]
__device__ __align__(16) __nv_bfloat16 g_mb2_lo[C * KCB];

#define SCALE_L2E 0.18033688011112042f   // 0.125 * log2(e)

// ---------------- helpers ----------------
__device__ __forceinline__ uint32_t smem_u32(const void* p) {
    uint32_t a;
    asm("{ .reg .u64 t; cvta.to.shared.u64 t, %1; cvt.u32.u64 %0, t; }" : "=r"(a) : "l"(p));
    return a;
}
__device__ __forceinline__ void mma16816(float* c,
        uint32_t a0, uint32_t a1, uint32_t a2, uint32_t a3,
        uint32_t b0, uint32_t b1) {
    asm volatile(
        "mma.sync.aligned.m16n8k16.row.col.f32.bf16.bf16.f32 "
        "{%0,%1,%2,%3}, {%4,%5,%6,%7}, {%8,%9}, {%0,%1,%2,%3};"
        : "+f"(c[0]), "+f"(c[1]), "+f"(c[2]), "+f"(c[3])
        : "r"(a0), "r"(a1), "r"(a2), "r"(a3), "r"(b0), "r"(b1));
}
#define LDSM4(r, addr) \
    asm volatile("ldmatrix.sync.aligned.m8n8.x4.shared.b16 {%0,%1,%2,%3}, [%4];" \
        : "=r"((r)[0]), "=r"((r)[1]), "=r"((r)[2]), "=r"((r)[3]) : "r"(addr))
__device__ __forceinline__ float ex2f(float x) {
    float r;
    asm("ex2.approx.ftz.f32 %0, %1;" : "=f"(r) : "f"(x));
    return r;
}
__device__ __forceinline__ uint32_t pack2(float a, float b) {
    __nv_bfloat162 h = __floats2bfloat162_rn(a, b);
    return *reinterpret_cast<uint32_t*>(&h);
}

// ---------------- K1: GroupNorm stats ----------------
__global__ void gn_stats_kernel(const float* __restrict__ x) {
    int bg = blockIdx.x;
    const float4* p = (const float4*)(x + (size_t)bg * (2 * HW));
    float s = 0.f, ss = 0.f;
    #pragma unroll 4
    for (int i = threadIdx.x; i < (2 * HW) / 4; i += blockDim.x) {
        float4 v = p[i];
        s  += (v.x + v.y) + (v.z + v.w);
        ss += (v.x * v.x + v.y * v.y) + (v.z * v.z + v.w * v.w);
    }
    #pragma unroll
    for (int o = 16; o; o >>= 1) {
        s  += __shfl_xor_sync(0xFFFFFFFFu, s, o);
        ss += __shfl_xor_sync(0xFFFFFFFFu, ss, o);
    }
    __shared__ float sm1[8], sm2[8];
    int w = threadIdx.x >> 5;
    if ((threadIdx.x & 31) == 0) { sm1[w] = s; sm2[w] = ss; }
    __syncthreads();
    if (threadIdx.x == 0) {
        float ts = 0.f, tss = 0.f;
        #pragma unroll
        for (int i = 0; i < 8; i++) { ts += sm1[i]; tss += sm2[i]; }
        const float inv = 1.f / (float)(2 * HW);
        float mean = ts * inv;
        float var  = tss * inv - mean * mean;
        g_mean[bg] = mean;
        g_rstd[bg] = rsqrtf(var + 1e-6f);
    }
}

// ---------------- K2: GN fold + folded phi bias ----------------
__global__ void prep0_kernel(const float* __restrict__ phi_w, const float* __restrict__ phi_b,
                             const float* __restrict__ gn_w, const float* __restrict__ gn_b) {
    int b = blockIdx.x, c = threadIdx.x;
    __shared__ float shB[C];
    int g = c >> 1;
    float a = g_rstd[b * NG + g] * gn_w[c];
    g_scA[b * C + c] = a;
    shB[c] = gn_b[c] - g_mean[b * NG + g] * a;
    __syncthreads();
    float acc = phi_b[c];
    #pragma unroll
    for (int j = 0; j < C; j++) acc += phi_w[c * C + j] * shB[j];
    g_bias2[b * C + c] = acc;
}

// ---------------- K3: G[k][c] = 0.125*log2e * (phi^T @ mb) ----------------
__global__ void prepG_kernel(const float* __restrict__ phi_w, const float* __restrict__ mb) {
    int k = blockIdx.x, c = threadIdx.x;
    float a0 = 0.f, a1 = 0.f, a2 = 0.f, a3 = 0.f;
    #pragma unroll
    for (int o = 0; o < C; o += 4) {
        a0 += phi_w[(o + 0) * C + c] * mb[(o + 0) * KCB + k];
        a1 += phi_w[(o + 1) * C + c] * mb[(o + 1) * KCB + k];
        a2 += phi_w[(o + 2) * C + c] * mb[(o + 2) * KCB + k];
        a3 += phi_w[(o + 3) * C + c] * mb[(o + 3) * KCB + k];
    }
    g_G[k * C + c] = SCALE_L2E * ((a0 + a1) + (a2 + a3));
}

// ---------------- K4: per-batch scale/split of G + sbias ----------------
__global__ void prep_scale_kernel(const float* __restrict__ mb) {
    int k = blockIdx.x, b = blockIdx.y, c = threadIdx.x;
    float v = g_scA[b * C + c] * g_G[k * C + c];
    __nv_bfloat16 hi = __float2bfloat16(v);
    __nv_bfloat16 lo = __float2bfloat16(v - __bfloat162float(hi));
    g_W2T_hi[b * (KCB * C) + k * C + c] = hi;
    g_W2T_lo[b * (KCB * C) + k * C + c] = lo;

    float p = g_bias2[b * C + c] * mb[c * KCB + k];
    #pragma unroll
    for (int o = 16; o; o >>= 1) p += __shfl_xor_sync(0xFFFFFFFFu, p, o);
    __shared__ float ws[2];
    if ((c & 31) == 0) ws[c >> 5] = p;
    __syncthreads();
    if (c == 0) g_sbias[b * KCB + k] = SCALE_L2E * (ws[0] + ws[1]);
}

// ---------------- K5: mb2[o][k] = wz_w @ mb split planes ----------------
__global__ void prep2_kernel(const float* __restrict__ wz_w, const float* __restrict__ mb) {
    int k = blockIdx.x, o = threadIdx.x;
    float a0 = 0.f, a1 = 0.f, a2 = 0.f, a3 = 0.f;
    #pragma unroll
    for (int c = 0; c < C; c += 4) {
        a0 += wz_w[o * C + c + 0] * mb[(c + 0) * KCB + k];
        a1 += wz_w[o * C + c + 1] * mb[(c + 1) * KCB + k];
        a2 += wz_w[o * C + c + 2] * mb[(c + 2) * KCB + k];
        a3 += wz_w[o * C + c + 3] * mb[(c + 3) * KCB + k];
    }
    float acc = (a0 + a1) + (a2 + a3);
    __nv_bfloat16 hi = __float2bfloat16(acc);
    __nv_bfloat16 lo = __float2bfloat16(acc - __bfloat162float(hi));
    g_mb2_hi[o * KCB + k] = hi;
    g_mb2_lo[o * KCB + k] = lo;
}

// ---------------- weight chunk prefetch via cp.async ----------------
__device__ __forceinline__ void prefetch_chunk(int ci, int st, int b, int tid, uint32_t smb) {
    #pragma unroll
    for (int t = 0; t < 8; t++) {
        int idx = tid + t * 256;
        int plane = idx >> 9, rem = idx & 511, row = rem >> 3, seg = rem & 7;
        const __nv_bfloat16* src;
        if      (plane == 0) src = g_W2T_hi + b * (KCB * C) + (ci * 64 + row) * 64 + seg * 8;
        else if (plane == 1) src = g_W2T_lo + b * (KCB * C) + (ci * 64 + row) * 64 + seg * 8;
        else if (plane == 2) src = g_mb2_hi + row * KCB + ci * 64 + seg * 8;
        else                 src = g_mb2_lo + row * KCB + ci * 64 + seg * 8;
        uint32_t dst = smb + WB_OFF + st * 36864 + plane * 9216 + row * 144 + seg * 16;
        asm volatile("cp.async.ca.shared.global [%0], [%1], 16;" :: "r"(dst), "l"(src) : "memory");
    }
}

// ---------------- K6: main fused kernel (16 tok/warp, 2 CTAs/SM) ----------------
__global__ __launch_bounds__(THREADS, 2)
void fused_main_kernel(const float* __restrict__ x, float* __restrict__ out,
                       const float* __restrict__ wz_b) {
    extern __shared__ char S[];
    const int tid = threadIdx.x, wid = tid >> 5, lane = tid & 31;
    const int g = lane >> 2, tq = lane & 3;
    const int b = blockIdx.y;
    const int tok0 = blockIdx.x * TOKT;
    const int wtok = wid * 16;
    const uint32_t smb = smem_u32(S);

    prefetch_chunk(0, 0, b, tid, smb);
    asm volatile("cp.async.commit_group;" ::: "memory");
    prefetch_chunk(1, 1, b, tid, smb);
    asm volatile("cp.async.commit_group;" ::: "memory");

    if (tid < C) ((float*)(S + WZB_OFF))[tid] = wz_b[tid];
    for (int i = tid; i < KCB; i += THREADS)
        ((float*)(S + SB_OFF))[i] = g_sbias[b * KCB + i];

    // ---- A fragments (hi/lo split) built directly from global x ----
    // frag map (m16n8k16 row-A): a0=(row0, c0:c0+1), a1=(row1, ..), a2=(row0, c0+8..), a3=(row1, c0+8..)
    const float* xg = x + (size_t)b * C * HW + tok0;
    uint32_t ah[4][4], al[4][4];
    {
        const int row0 = wtok + g, row1 = row0 + 8;
        #pragma unroll
        for (int kt = 0; kt < 4; kt++) {
            #pragma unroll
            for (int half = 0; half < 2; half++) {
                int c0 = kt * 16 + tq * 2 + half * 8;
                float v00 = xg[(size_t)c0 * HW + row0];
                float v01 = xg[(size_t)(c0 + 1) * HW + row0];
                float v10 = xg[(size_t)c0 * HW + row1];
                float v11 = xg[(size_t)(c0 + 1) * HW + row1];
                __nv_bfloat162 h0 = __floats2bfloat162_rn(v00, v01);
                __nv_bfloat162 h1 = __floats2bfloat162_rn(v10, v11);
                ah[kt][half * 2]     = *reinterpret_cast<uint32_t*>(&h0);
                ah[kt][half * 2 + 1] = *reinterpret_cast<uint32_t*>(&h1);
                al[kt][half * 2]     = pack2(v00 - __low2float(h0), v01 - __high2float(h0));
                al[kt][half * 2 + 1] = pack2(v10 - __low2float(h1), v11 - __high2float(h1));
            }
        }
    }

    float yacc[8][4];
    #pragma unroll
    for (int nt = 0; nt < 8; nt++)
        #pragma unroll
        for (int q = 0; q < 4; q++) yacc[nt][q] = 0.f;
    float zacc[2] = {0.f, 0.f};

    const uint32_t brow = (uint32_t)(lane & 7) * 144 + (uint32_t)((lane >> 3) * 16);

    for (int ci = 0; ci < 8; ci++) {
        if (ci < 7) asm volatile("cp.async.wait_group 1;" ::: "memory");
        else        asm volatile("cp.async.wait_group 0;" ::: "memory");
        __syncthreads();

        const uint32_t stg = smb + WB_OFF + (uint32_t)((ci & 1) * 36864);
        const uint32_t Wh = stg, Wl = stg + 9216, Mh = stg + 18432, Ml = stg + 27648;
        const float* sbp = (const float*)(S + SB_OFF) + ci * 64;

        // ---- GEMM2 + fused exp: per nt, 12 mma then ex2/pack ----
        uint32_t eh[8], eh2[8], el[8], el2[8];
        #pragma unroll
        for (int nt = 0; nt < 8; nt++) {
            uint32_t radr = (uint32_t)(nt * 8) * 144 + brow;
            uint32_t bh[8], bl[8];
            LDSM4(bh,     Wh + radr);
            LDSM4(bh + 4, Wh + radr + 64);
            LDSM4(bl,     Wl + radr);
            LDSM4(bl + 4, Wl + radr + 64);
            float sc[4] = {0.f, 0.f, 0.f, 0.f};
            #pragma unroll
            for (int kt = 0; kt < 4; kt++) {
                mma16816(sc, ah[kt][0], ah[kt][1], ah[kt][2], ah[kt][3], bh[2 * kt], bh[2 * kt + 1]);
                mma16816(sc, al[kt][0], al[kt][1], al[kt][2], al[kt][3], bh[2 * kt], bh[2 * kt + 1]);
                mma16816(sc, ah[kt][0], ah[kt][1], ah[kt][2], ah[kt][3], bl[2 * kt], bl[2 * kt + 1]);
            }
            float sbx = sbp[nt * 8 + 2 * tq];
            float sby = sbp[nt * 8 + 2 * tq + 1];
            float e0 = ex2f(sc[0] + sbx);
            float e1 = ex2f(sc[1] + sby);
            float e2 = ex2f(sc[2] + sbx);
            float e3 = ex2f(sc[3] + sby);
            zacc[0] += e0 + e1;
            zacc[1] += e2 + e3;
            __nv_bfloat162 h01 = __floats2bfloat162_rn(e0, e1);
            __nv_bfloat162 h23 = __floats2bfloat162_rn(e2, e3);
            eh[nt]  = *reinterpret_cast<uint32_t*>(&h01);
            eh2[nt] = *reinterpret_cast<uint32_t*>(&h23);
            el[nt]  = pack2(e0 - __low2float(h01), e1 - __high2float(h01));
            el2[nt] = pack2(e2 - __low2float(h23), e3 - __high2float(h23));
        }

        // ---- GEMM3: y += E @ mb2^T, 3 split products ----
        #pragma unroll
        for (int nt = 0; nt < 8; nt++) {
            uint32_t radr = (uint32_t)(nt * 8) * 144 + brow;
            uint32_t mh[8], ml[8];
            LDSM4(mh,     Mh + radr);
            LDSM4(mh + 4, Mh + radr + 64);
            LDSM4(ml,     Ml + radr);
            LDSM4(ml + 4, Ml + radr + 64);
            #pragma unroll
            for (int kt = 0; kt < 4; kt++) {
                uint32_t a0 = eh[2 * kt],      a1 = eh2[2 * kt];
                uint32_t a2 = eh[2 * kt + 1],  a3 = eh2[2 * kt + 1];
                uint32_t l0 = el[2 * kt],      l1 = el2[2 * kt];
                uint32_t l2 = el[2 * kt + 1],  l3 = el2[2 * kt + 1];
                mma16816(yacc[nt], a0, a1, a2, a3, mh[2 * kt], mh[2 * kt + 1]);
                mma16816(yacc[nt], l0, l1, l2, l3, mh[2 * kt], mh[2 * kt + 1]);
                mma16816(yacc[nt], a0, a1, a2, a3, ml[2 * kt], ml[2 * kt + 1]);
            }
        }

        __syncthreads();
        if (ci + 2 < 8) {
            prefetch_chunk(ci + 2, ci & 1, b, tid, smb);
            asm volatile("cp.async.commit_group;" ::: "memory");
        }
    }

    // row-sum Z over quad lanes
    #pragma unroll
    for (int q = 0; q < 2; q++) {
        zacc[q] += __shfl_xor_sync(0xFFFFFFFFu, zacc[q], 1);
        zacc[q] += __shfl_xor_sync(0xFFFFFFFFu, zacc[q], 2);
    }
    float* ZRp = (float*)(S + ZR_OFF);
    if (tq == 0) {
        ZRp[wtok + g]     = zacc[0];
        ZRp[wtok + 8 + g] = zacc[1];
    }
    __syncwarp();
    float iz0 = 1.f / ZRp[wtok + g];
    float iz1 = 1.f / ZRp[wtok + 8 + g];

    // stage y to smem [o][tok] (pad 132) in stage0 region for coalesced output
    float* YS = (float*)S;
    __syncthreads();
    {
        int r0 = wtok + g;
        #pragma unroll
        for (int nt = 0; nt < 8; nt++) {
            int o0 = nt * 8 + 2 * tq;
            YS[o0 * 132 + r0]           = yacc[nt][0] * iz0;
            YS[(o0 + 1) * 132 + r0]     = yacc[nt][1] * iz0;
            YS[o0 * 132 + r0 + 8]       = yacc[nt][2] * iz1;
            YS[(o0 + 1) * 132 + r0 + 8] = yacc[nt][3] * iz1;
        }
    }
    __syncthreads();

    // out = y + wz_b + residual, coalesced float4
    const float* wzp = (const float*)(S + WZB_OFF);
    float* og = out + (size_t)b * C * HW + tok0;
    #pragma unroll
    for (int it = 0; it < 8; it++) {
        int i = tid + it * 256;
        int o = i >> 5, t32 = i & 31;
        float4 ys = *(const float4*)(YS + o * 132 + t32 * 4);
        float4 xr = *(const float4*)(xg + (size_t)o * HW + t32 * 4);
        float wb = wzp[o];
        float4 r;
        r.x = ys.x + xr.x + wb;
        r.y = ys.y + xr.y + wb;
        r.z = ys.z + xr.z + wb;
        r.w = ys.w + xr.w + wb;
        *(float4*)(og + (size_t)o * HW + t32 * 4) = r;
    }
}

// ---------------------------------------------------------------------------
extern "C" void kernel_launch(void* const* d_in, const int* in_sizes, int n_in,
                              void* d_out, int out_size) {
    const float* x     = (const float*)d_in[0];
    const float* mb    = (const float*)d_in[1];
    const float* phi_w = (const float*)d_in[2];
    const float* phi_b = (const float*)d_in[3];
    const float* gn_w  = (const float*)d_in[4];
    const float* gn_b  = (const float*)d_in[5];
    const float* wz_w  = (const float*)d_in[6];
    const float* wz_b  = (const float*)d_in[7];
    float* out = (float*)d_out;

    cudaFuncSetAttribute(fused_main_kernel,
                         cudaFuncAttributeMaxDynamicSharedMemorySize, SMEM_TOTAL);

    gn_stats_kernel<<<NB * NG, 256>>>(x);
    prep0_kernel<<<NB, C>>>(phi_w, phi_b, gn_w, gn_b);
    prepG_kernel<<<KCB, C>>>(phi_w, mb);
    {
        dim3 gs(KCB, NB);
        prep_scale_kernel<<<gs, C>>>(mb);
    }
    prep2_kernel<<<KCB, C>>>(wz_w, mb);

    dim3 grid(HW / TOKT, NB);
    fused_main_kernel<<<grid, THREADS, SMEM_TOTAL>>>(x, out, wz_b);
}

// round 8
// speedup vs baseline: 2.9447x; 1.8069x over previous
#include <cuda_runtime.h>
#include <cuda_fp16.h>
#include <cstdint>

#define NB   10
#define C    64
#define HW   16384
#define KCB  512
#define NG   32
#define TOKT 128
#define THREADS 256

// ---- smem layout (bytes from dynamic base) ----
#define WB_OFF   0                // 2 stages x (2 planes x 9216B) = 36864
#define SB_OFF   36864            // sbias 512 f32 = 2048
#define ZR_OFF   38912            // zrow 128 f32 = 512
#define WZB_OFF  39424            // wz_b 64 f32 = 256
#define SMEM_TOTAL 39680
// epilogue y-stage reuses [0 .. 33792): 64 rows x 132 f32

// ---------------- device-global scratch ----------------
__device__ float g_mean[NB * NG], g_rstd[NB * NG];
__device__ float g_scA[NB * C], g_bias2[NB * C];
__device__ float g_G[KCB * C];                              // [k][c], incl 0.125*log2e
__device__ float g_sbias[NB * KCB];                         // incl 0.125*log2e
__device__ __align__(16) __half g_W2T[NB * KCB * C];        // [b][k][c] fp16
__device__ __align__(16) __half g_mb2[C * KCB];             // [o][k]   fp16

#define SCALE_L2E 0.18033688011112042f   // 0.125 * log2(e)

// ---------------- helpers ----------------
__device__ __forceinline__ uint32_t smem_u32(const void* p) {
    uint32_t a;
    asm("{ .reg .u64 t; cvta.to.shared.u64 t, %1; cvt.u32.u64 %0, t; }" : "=r"(a) : "l"(p));
    return a;
}
__device__ __forceinline__ void mma16816(float* c,
        uint32_t a0, uint32_t a1, uint32_t a2, uint32_t a3,
        uint32_t b0, uint32_t b1) {
    asm volatile(
        "mma.sync.aligned.m16n8k16.row.col.f32.f16.f16.f32 "
        "{%0,%1,%2,%3}, {%4,%5,%6,%7}, {%8,%9}, {%0,%1,%2,%3};"
        : "+f"(c[0]), "+f"(c[1]), "+f"(c[2]), "+f"(c[3])
        : "r"(a0), "r"(a1), "r"(a2), "r"(a3), "r"(b0), "r"(b1));
}
#define LDSM4(r, addr) \
    asm volatile("ldmatrix.sync.aligned.m8n8.x4.shared.b16 {%0,%1,%2,%3}, [%4];" \
        : "=r"((r)[0]), "=r"((r)[1]), "=r"((r)[2]), "=r"((r)[3]) : "r"(addr))
__device__ __forceinline__ float ex2f(float x) {
    float r;
    asm("ex2.approx.ftz.f32 %0, %1;" : "=f"(r) : "f"(x));
    return r;
}
__device__ __forceinline__ uint32_t packh2(float a, float b) {
    __half2 h = __floats2half2_rn(a, b);
    return *reinterpret_cast<uint32_t*>(&h);
}

// ---------------- K1: GroupNorm stats ----------------
__global__ void gn_stats_kernel(const float* __restrict__ x) {
    int bg = blockIdx.x;
    const float4* p = (const float4*)(x + (size_t)bg * (2 * HW));
    float s = 0.f, ss = 0.f;
    #pragma unroll 4
    for (int i = threadIdx.x; i < (2 * HW) / 4; i += blockDim.x) {
        float4 v = p[i];
        s  += (v.x + v.y) + (v.z + v.w);
        ss += (v.x * v.x + v.y * v.y) + (v.z * v.z + v.w * v.w);
    }
    #pragma unroll
    for (int o = 16; o; o >>= 1) {
        s  += __shfl_xor_sync(0xFFFFFFFFu, s, o);
        ss += __shfl_xor_sync(0xFFFFFFFFu, ss, o);
    }
    __shared__ float sm1[8], sm2[8];
    int w = threadIdx.x >> 5;
    if ((threadIdx.x & 31) == 0) { sm1[w] = s; sm2[w] = ss; }
    __syncthreads();
    if (threadIdx.x == 0) {
        float ts = 0.f, tss = 0.f;
        #pragma unroll
        for (int i = 0; i < 8; i++) { ts += sm1[i]; tss += sm2[i]; }
        const float inv = 1.f / (float)(2 * HW);
        float mean = ts * inv;
        float var  = tss * inv - mean * mean;
        g_mean[bg] = mean;
        g_rstd[bg] = rsqrtf(var + 1e-6f);
    }
}

// ---------------- K2: GN fold + folded phi bias ----------------
__global__ void prep0_kernel(const float* __restrict__ phi_w, const float* __restrict__ phi_b,
                             const float* __restrict__ gn_w, const float* __restrict__ gn_b) {
    int b = blockIdx.x, c = threadIdx.x;
    __shared__ float shB[C];
    int g = c >> 1;
    float a = g_rstd[b * NG + g] * gn_w[c];
    g_scA[b * C + c] = a;
    shB[c] = gn_b[c] - g_mean[b * NG + g] * a;
    __syncthreads();
    float acc = phi_b[c];
    #pragma unroll
    for (int j = 0; j < C; j++) acc += phi_w[c * C + j] * shB[j];
    g_bias2[b * C + c] = acc;
}

// ---------------- K3: G[k][c] = 0.125*log2e * (phi^T @ mb) ----------------
__global__ void prepG_kernel(const float* __restrict__ phi_w, const float* __restrict__ mb) {
    int k = blockIdx.x, c = threadIdx.x;
    float a0 = 0.f, a1 = 0.f, a2 = 0.f, a3 = 0.f;
    #pragma unroll
    for (int o = 0; o < C; o += 4) {
        a0 += phi_w[(o + 0) * C + c] * mb[(o + 0) * KCB + k];
        a1 += phi_w[(o + 1) * C + c] * mb[(o + 1) * KCB + k];
        a2 += phi_w[(o + 2) * C + c] * mb[(o + 2) * KCB + k];
        a3 += phi_w[(o + 3) * C + c] * mb[(o + 3) * KCB + k];
    }
    g_G[k * C + c] = SCALE_L2E * ((a0 + a1) + (a2 + a3));
}

// ---------------- K4: per-batch fp16 W2T + sbias ----------------
__global__ void prep_scale_kernel(const float* __restrict__ mb) {
    int k = blockIdx.x, b = blockIdx.y, c = threadIdx.x;
    float v = g_scA[b * C + c] * g_G[k * C + c];
    g_W2T[b * (KCB * C) + k * C + c] = __float2half(v);

    float p = g_bias2[b * C + c] * mb[c * KCB + k];
    #pragma unroll
    for (int o = 16; o; o >>= 1) p += __shfl_xor_sync(0xFFFFFFFFu, p, o);
    __shared__ float ws[2];
    if ((c & 31) == 0) ws[c >> 5] = p;
    __syncthreads();
    if (c == 0) g_sbias[b * KCB + k] = SCALE_L2E * (ws[0] + ws[1]);
}

// ---------------- K5: mb2[o][k] = wz_w @ mb (fp16) ----------------
__global__ void prep2_kernel(const float* __restrict__ wz_w, const float* __restrict__ mb) {
    int k = blockIdx.x, o = threadIdx.x;
    float a0 = 0.f, a1 = 0.f, a2 = 0.f, a3 = 0.f;
    #pragma unroll
    for (int c = 0; c < C; c += 4) {
        a0 += wz_w[o * C + c + 0] * mb[(c + 0) * KCB + k];
        a1 += wz_w[o * C + c + 1] * mb[(c + 1) * KCB + k];
        a2 += wz_w[o * C + c + 2] * mb[(c + 2) * KCB + k];
        a3 += wz_w[o * C + c + 3] * mb[(c + 3) * KCB + k];
    }
    g_mb2[o * KCB + k] = __float2half((a0 + a1) + (a2 + a3));
}

// ---------------- weight chunk prefetch via cp.async ----------------
// plane 0: W2T chunk [64k x 64c], plane 1: mb2 chunk [64o x 64k]; rows padded to 144B
__device__ __forceinline__ void prefetch_chunk(int ci, int st, int b, int tid, uint32_t smb) {
    #pragma unroll
    for (int t = 0; t < 4; t++) {
        int idx = tid + t * 256;
        int plane = idx >> 9, rem = idx & 511, row = rem >> 3, seg = rem & 7;
        const __half* src;
        if (plane == 0) src = g_W2T + b * (KCB * C) + (ci * 64 + row) * 64 + seg * 8;
        else            src = g_mb2 + row * KCB + ci * 64 + seg * 8;
        uint32_t dst = smb + WB_OFF + st * 18432 + plane * 9216 + row * 144 + seg * 16;
        asm volatile("cp.async.ca.shared.global [%0], [%1], 16;" :: "r"(dst), "l"(src) : "memory");
    }
}

// ---------------- K6: main fused kernel (fp16 single-product) ----------------
__global__ __launch_bounds__(THREADS, 2)
void fused_main_kernel(const float* __restrict__ x, float* __restrict__ out,
                       const float* __restrict__ wz_b) {
    extern __shared__ char S[];
    const int tid = threadIdx.x, wid = tid >> 5, lane = tid & 31;
    const int g = lane >> 2, tq = lane & 3;
    const int b = blockIdx.y;
    const int tok0 = blockIdx.x * TOKT;
    const int wtok = wid * 16;
    const uint32_t smb = smem_u32(S);

    prefetch_chunk(0, 0, b, tid, smb);
    asm volatile("cp.async.commit_group;" ::: "memory");
    prefetch_chunk(1, 1, b, tid, smb);
    asm volatile("cp.async.commit_group;" ::: "memory");

    if (tid < C) ((float*)(S + WZB_OFF))[tid] = wz_b[tid];
    for (int i = tid; i < KCB; i += THREADS)
        ((float*)(S + SB_OFF))[i] = g_sbias[b * KCB + i];

    // ---- A fragments (fp16) built directly from global x ----
    const float* xg = x + (size_t)b * C * HW + tok0;
    uint32_t ah[4][4];
    {
        const int row0 = wtok + g, row1 = row0 + 8;
        #pragma unroll
        for (int kt = 0; kt < 4; kt++) {
            #pragma unroll
            for (int half = 0; half < 2; half++) {
                int c0 = kt * 16 + tq * 2 + half * 8;
                float v00 = xg[(size_t)c0 * HW + row0];
                float v01 = xg[(size_t)(c0 + 1) * HW + row0];
                float v10 = xg[(size_t)c0 * HW + row1];
                float v11 = xg[(size_t)(c0 + 1) * HW + row1];
                ah[kt][half * 2]     = packh2(v00, v01);
                ah[kt][half * 2 + 1] = packh2(v10, v11);
            }
        }
    }

    float yacc[8][4];
    #pragma unroll
    for (int nt = 0; nt < 8; nt++)
        #pragma unroll
        for (int q = 0; q < 4; q++) yacc[nt][q] = 0.f;
    float zacc[2] = {0.f, 0.f};

    const uint32_t brow = (uint32_t)(lane & 7) * 144 + (uint32_t)((lane >> 3) * 16);

    for (int ci = 0; ci < 8; ci++) {
        if (ci < 7) asm volatile("cp.async.wait_group 1;" ::: "memory");
        else        asm volatile("cp.async.wait_group 0;" ::: "memory");
        __syncthreads();

        const uint32_t stg = smb + WB_OFF + (uint32_t)((ci & 1) * 18432);
        const uint32_t Wh = stg, Mh = stg + 9216;
        const float* sbp = (const float*)(S + SB_OFF) + ci * 64;

        // ---- GEMM2 + fused exp ----
        uint32_t eh[8], eh2[8];
        #pragma unroll
        for (int nt = 0; nt < 8; nt++) {
            uint32_t radr = (uint32_t)(nt * 8) * 144 + brow;
            uint32_t bh[8];
            LDSM4(bh,     Wh + radr);
            LDSM4(bh + 4, Wh + radr + 64);
            float sc[4] = {0.f, 0.f, 0.f, 0.f};
            #pragma unroll
            for (int kt = 0; kt < 4; kt++)
                mma16816(sc, ah[kt][0], ah[kt][1], ah[kt][2], ah[kt][3], bh[2 * kt], bh[2 * kt + 1]);
            float sbx = sbp[nt * 8 + 2 * tq];
            float sby = sbp[nt * 8 + 2 * tq + 1];
            float e0 = ex2f(sc[0] + sbx);
            float e1 = ex2f(sc[1] + sby);
            float e2 = ex2f(sc[2] + sbx);
            float e3 = ex2f(sc[3] + sby);
            zacc[0] += e0 + e1;
            zacc[1] += e2 + e3;
            eh[nt]  = packh2(e0, e1);
            eh2[nt] = packh2(e2, e3);
        }

        // ---- GEMM3: y += E @ mb2^T ----
        #pragma unroll
        for (int nt = 0; nt < 8; nt++) {
            uint32_t radr = (uint32_t)(nt * 8) * 144 + brow;
            uint32_t mh[8];
            LDSM4(mh,     Mh + radr);
            LDSM4(mh + 4, Mh + radr + 64);
            #pragma unroll
            for (int kt = 0; kt < 4; kt++) {
                mma16816(yacc[nt], eh[2 * kt], eh2[2 * kt], eh[2 * kt + 1], eh2[2 * kt + 1],
                         mh[2 * kt], mh[2 * kt + 1]);
            }
        }

        __syncthreads();
        if (ci + 2 < 8) {
            prefetch_chunk(ci + 2, ci & 1, b, tid, smb);
            asm volatile("cp.async.commit_group;" ::: "memory");
        }
    }

    // row-sum Z over quad lanes
    #pragma unroll
    for (int q = 0; q < 2; q++) {
        zacc[q] += __shfl_xor_sync(0xFFFFFFFFu, zacc[q], 1);
        zacc[q] += __shfl_xor_sync(0xFFFFFFFFu, zacc[q], 2);
    }
    float* ZRp = (float*)(S + ZR_OFF);
    if (tq == 0) {
        ZRp[wtok + g]     = zacc[0];
        ZRp[wtok + 8 + g] = zacc[1];
    }
    __syncwarp();
    float iz0 = 1.f / ZRp[wtok + g];
    float iz1 = 1.f / ZRp[wtok + 8 + g];

    // stage y to smem [o][tok] (pad 132) for coalesced output
    float* YS = (float*)S;
    __syncthreads();
    {
        int r0 = wtok + g;
        #pragma unroll
        for (int nt = 0; nt < 8; nt++) {
            int o0 = nt * 8 + 2 * tq;
            YS[o0 * 132 + r0]           = yacc[nt][0] * iz0;
            YS[(o0 + 1) * 132 + r0]     = yacc[nt][1] * iz0;
            YS[o0 * 132 + r0 + 8]       = yacc[nt][2] * iz1;
            YS[(o0 + 1) * 132 + r0 + 8] = yacc[nt][3] * iz1;
        }
    }
    __syncthreads();

    // out = y + wz_b + residual, coalesced float4
    const float* wzp = (const float*)(S + WZB_OFF);
    float* og = out + (size_t)b * C * HW + tok0;
    #pragma unroll
    for (int it = 0; it < 8; it++) {
        int i = tid + it * 256;
        int o = i >> 5, t32 = i & 31;
        float4 ys = *(const float4*)(YS + o * 132 + t32 * 4);
        float4 xr = *(const float4*)(xg + (size_t)o * HW + t32 * 4);
        float wb = wzp[o];
        float4 r;
        r.x = ys.x + xr.x + wb;
        r.y = ys.y + xr.y + wb;
        r.z = ys.z + xr.z + wb;
        r.w = ys.w + xr.w + wb;
        *(float4*)(og + (size_t)o * HW + t32 * 4) = r;
    }
}

// ---------------------------------------------------------------------------
extern "C" void kernel_launch(void* const* d_in, const int* in_sizes, int n_in,
                              void* d_out, int out_size) {
    const float* x     = (const float*)d_in[0];
    const float* mb    = (const float*)d_in[1];
    const float* phi_w = (const float*)d_in[2];
    const float* phi_b = (const float*)d_in[3];
    const float* gn_w  = (const float*)d_in[4];
    const float* gn_b  = (const float*)d_in[5];
    const float* wz_w  = (const float*)d_in[6];
    const float* wz_b  = (const float*)d_in[7];
    float* out = (float*)d_out;

    cudaFuncSetAttribute(fused_main_kernel,
                         cudaFuncAttributeMaxDynamicSharedMemorySize, SMEM_TOTAL);

    gn_stats_kernel<<<NB * NG, 256>>>(x);
    prep0_kernel<<<NB, C>>>(phi_w, phi_b, gn_w, gn_b);
    prepG_kernel<<<KCB, C>>>(phi_w, mb);
    {
        dim3 gs(KCB, NB);
        prep_scale_kernel<<<gs, C>>>(mb);
    }
    prep2_kernel<<<KCB, C>>>(wz_w, mb);

    dim3 grid(HW / TOKT, NB);
    fused_main_kernel<<<grid, THREADS, SMEM_TOTAL>>>(x, out, wz_b);
}

// round 9
// speedup vs baseline: 3.0794x; 1.0457x over previous
#include <cuda_runtime.h>
#include <cuda_fp16.h>
#include <cstdint>

#define NB   10
#define C    64
#define HW   16384
#define KCB  512
#define NG   32
#define TOKT 128
#define THREADS 256

// ---- main-kernel smem layout (bytes from dynamic base) ----
#define WB_OFF   0                // 2 stages x (2 planes x 9216B) = 36864
#define SB_OFF   36864            // sbias 512 f32 = 2048
#define ZR_OFF   38912            // zrow 128 f32 = 512
#define WZB_OFF  39424            // wz_b 64 f32 = 256
#define SMEM_TOTAL 39680
// epilogue y-stage reuses [0 .. 33792): 64 rows x 132 f32

// ---------------- device-global scratch ----------------
__device__ float g_mean[NB * NG], g_rstd[NB * NG];
__device__ float g_scA[NB * C], g_bias2[NB * C];
__device__ float g_sbias[NB * KCB];                         // incl 0.125*log2e
__device__ __align__(16) __half g_W2T[NB * KCB * C];        // [b][k][c] fp16
__device__ __align__(16) __half g_mb2[C * KCB];             // [o][k]   fp16

#define SCALE_L2E 0.18033688011112042f   // 0.125 * log2(e)

// ---------------- helpers ----------------
__device__ __forceinline__ uint32_t smem_u32(const void* p) {
    uint32_t a;
    asm("{ .reg .u64 t; cvta.to.shared.u64 t, %1; cvt.u32.u64 %0, t; }" : "=r"(a) : "l"(p));
    return a;
}
__device__ __forceinline__ void mma16816(float* c,
        uint32_t a0, uint32_t a1, uint32_t a2, uint32_t a3,
        uint32_t b0, uint32_t b1) {
    asm volatile(
        "mma.sync.aligned.m16n8k16.row.col.f32.f16.f16.f32 "
        "{%0,%1,%2,%3}, {%4,%5,%6,%7}, {%8,%9}, {%0,%1,%2,%3};"
        : "+f"(c[0]), "+f"(c[1]), "+f"(c[2]), "+f"(c[3])
        : "r"(a0), "r"(a1), "r"(a2), "r"(a3), "r"(b0), "r"(b1));
}
#define LDSM4(r, addr) \
    asm volatile("ldmatrix.sync.aligned.m8n8.x4.shared.b16 {%0,%1,%2,%3}, [%4];" \
        : "=r"((r)[0]), "=r"((r)[1]), "=r"((r)[2]), "=r"((r)[3]) : "r"(addr))
__device__ __forceinline__ float ex2f(float x) {
    float r;
    asm("ex2.approx.ftz.f32 %0, %1;" : "=f"(r) : "f"(x));
    return r;
}
__device__ __forceinline__ uint32_t packh2(float a, float b) {
    __half2 h = __floats2half2_rn(a, b);
    return *reinterpret_cast<uint32_t*>(&h);
}

// ---------------- K1: GroupNorm stats ----------------
__global__ void gn_stats_kernel(const float* __restrict__ x) {
    int bg = blockIdx.x;
    const float4* p = (const float4*)(x + (size_t)bg * (2 * HW));
    float s = 0.f, ss = 0.f;
    #pragma unroll 4
    for (int i = threadIdx.x; i < (2 * HW) / 4; i += blockDim.x) {
        float4 v = p[i];
        s  += (v.x + v.y) + (v.z + v.w);
        ss += (v.x * v.x + v.y * v.y) + (v.z * v.z + v.w * v.w);
    }
    #pragma unroll
    for (int o = 16; o; o >>= 1) {
        s  += __shfl_xor_sync(0xFFFFFFFFu, s, o);
        ss += __shfl_xor_sync(0xFFFFFFFFu, ss, o);
    }
    __shared__ float sm1[8], sm2[8];
    int w = threadIdx.x >> 5;
    if ((threadIdx.x & 31) == 0) { sm1[w] = s; sm2[w] = ss; }
    __syncthreads();
    if (threadIdx.x == 0) {
        float ts = 0.f, tss = 0.f;
        #pragma unroll
        for (int i = 0; i < 8; i++) { ts += sm1[i]; tss += sm2[i]; }
        const float inv = 1.f / (float)(2 * HW);
        float mean = ts * inv;
        float var  = tss * inv - mean * mean;
        g_mean[bg] = mean;
        g_rstd[bg] = rsqrtf(var + 1e-6f);
    }
}

// ---------------- K2: GN fold + folded phi bias ----------------
__global__ void prep0_kernel(const float* __restrict__ phi_w, const float* __restrict__ phi_b,
                             const float* __restrict__ gn_w, const float* __restrict__ gn_b) {
    int b = blockIdx.x, c = threadIdx.x;
    __shared__ float shB[C];
    int g = c >> 1;
    float a = g_rstd[b * NG + g] * gn_w[c];
    g_scA[b * C + c] = a;
    shB[c] = gn_b[c] - g_mean[b * NG + g] * a;
    __syncthreads();
    float acc = phi_b[c];
    #pragma unroll
    for (int j = 0; j < C; j++) acc += phi_w[c * C + j] * shB[j];
    g_bias2[b * C + c] = acc;
}

// ---------------- K3: merged weight prep (one launch, tiled, coalesced) ----
// grid = KCB/64 blocks (one 64-wide k-tile each), 256 threads.
// smem: MT[64c][64k], PW[64o][64c], WZ[64o][64c], SC2[10][64], B2[10][64]
#define MP_MT   0
#define MP_PW   4096
#define MP_WZ   8192
#define MP_SC2  12288
#define MP_B2   12928
#define MP_FLOATS 13568
__global__ void merged_prep_kernel(const float* __restrict__ phi_w,
                                   const float* __restrict__ wz_w,
                                   const float* __restrict__ mb) {
    extern __shared__ float P[];
    const int tid = threadIdx.x;
    const int k0 = blockIdx.x * 64;

    // coalesced stages
    for (int i = tid; i < 4096; i += 256) {
        int c = i >> 6, kj = i & 63;
        P[MP_MT + i] = mb[c * KCB + k0 + kj];   // MT[c][kj]
        P[MP_PW + i] = phi_w[i];                // PW[o][c]
        P[MP_WZ + i] = wz_w[i];                 // WZ[o][c]
    }
    for (int i = tid; i < NB * C; i += 256) {
        P[MP_SC2 + i] = g_scA[i];
        P[MP_B2  + i] = g_bias2[i];
    }
    __syncthreads();

    // G[kj][c] = SCALE * sum_o PW[o][c]*MT[o][kj]; then W2T[b][k0+kj][c] for all b
    #pragma unroll 1
    for (int pass = 0; pass < 16; pass++) {
        int kj = (tid >> 6) + pass * 4;
        int c  = tid & 63;
        float a0 = 0.f, a1 = 0.f, a2 = 0.f, a3 = 0.f;
        #pragma unroll
        for (int o = 0; o < C; o += 4) {
            a0 += P[MP_PW + (o + 0) * 64 + c] * P[MP_MT + (o + 0) * 64 + kj];
            a1 += P[MP_PW + (o + 1) * 64 + c] * P[MP_MT + (o + 1) * 64 + kj];
            a2 += P[MP_PW + (o + 2) * 64 + c] * P[MP_MT + (o + 2) * 64 + kj];
            a3 += P[MP_PW + (o + 3) * 64 + c] * P[MP_MT + (o + 3) * 64 + kj];
        }
        float gval = SCALE_L2E * ((a0 + a1) + (a2 + a3));
        #pragma unroll
        for (int b = 0; b < NB; b++)
            g_W2T[b * (KCB * C) + (k0 + kj) * C + c] =
                __float2half(P[MP_SC2 + b * 64 + c] * gval);
    }

    // mb2[o][k0+kj] = sum_c WZ[o][c]*MT[c][kj]
    #pragma unroll 1
    for (int pass = 0; pass < 16; pass++) {
        int o  = (tid >> 6) + pass * 4;
        int kj = tid & 63;
        float a0 = 0.f, a1 = 0.f, a2 = 0.f, a3 = 0.f;
        #pragma unroll
        for (int c = 0; c < C; c += 4) {
            a0 += P[MP_WZ + o * 64 + c + 0] * P[MP_MT + (c + 0) * 64 + kj];
            a1 += P[MP_WZ + o * 64 + c + 1] * P[MP_MT + (c + 1) * 64 + kj];
            a2 += P[MP_WZ + o * 64 + c + 2] * P[MP_MT + (c + 2) * 64 + kj];
            a3 += P[MP_WZ + o * 64 + c + 3] * P[MP_MT + (c + 3) * 64 + kj];
        }
        g_mb2[o * KCB + k0 + kj] = __float2half((a0 + a1) + (a2 + a3));
    }

    // sbias[b][k0+kj] = SCALE * sum_c B2[b][c]*MT[c][kj]
    for (int idx = tid; idx < NB * 64; idx += 256) {
        int b = idx >> 6, kj = idx & 63;
        float a0 = 0.f, a1 = 0.f;
        #pragma unroll
        for (int c = 0; c < C; c += 2) {
            a0 += P[MP_B2 + b * 64 + c]     * P[MP_MT + c * 64 + kj];
            a1 += P[MP_B2 + b * 64 + c + 1] * P[MP_MT + (c + 1) * 64 + kj];
        }
        g_sbias[b * KCB + k0 + kj] = SCALE_L2E * (a0 + a1);
    }
}

// ---------------- weight chunk prefetch via cp.async ----------------
__device__ __forceinline__ void prefetch_chunk(int ci, int st, int b, int tid, uint32_t smb) {
    #pragma unroll
    for (int t = 0; t < 4; t++) {
        int idx = tid + t * 256;
        int plane = idx >> 9, rem = idx & 511, row = rem >> 3, seg = rem & 7;
        const __half* src;
        if (plane == 0) src = g_W2T + b * (KCB * C) + (ci * 64 + row) * 64 + seg * 8;
        else            src = g_mb2 + row * KCB + ci * 64 + seg * 8;
        uint32_t dst = smb + WB_OFF + st * 18432 + plane * 9216 + row * 144 + seg * 16;
        asm volatile("cp.async.ca.shared.global [%0], [%1], 16;" :: "r"(dst), "l"(src) : "memory");
    }
}

// ---------------- K4: main fused kernel (fp16 single-product) ----------------
__global__ __launch_bounds__(THREADS, 2)
void fused_main_kernel(const float* __restrict__ x, float* __restrict__ out,
                       const float* __restrict__ wz_b) {
    extern __shared__ char S[];
    const int tid = threadIdx.x, wid = tid >> 5, lane = tid & 31;
    const int g = lane >> 2, tq = lane & 3;
    const int b = blockIdx.y;
    const int tok0 = blockIdx.x * TOKT;
    const int wtok = wid * 16;
    const uint32_t smb = smem_u32(S);

    prefetch_chunk(0, 0, b, tid, smb);
    asm volatile("cp.async.commit_group;" ::: "memory");
    prefetch_chunk(1, 1, b, tid, smb);
    asm volatile("cp.async.commit_group;" ::: "memory");

    if (tid < C) ((float*)(S + WZB_OFF))[tid] = wz_b[tid];
    for (int i = tid; i < KCB; i += THREADS)
        ((float*)(S + SB_OFF))[i] = g_sbias[b * KCB + i];

    // ---- A fragments (fp16) built directly from global x ----
    const float* xg = x + (size_t)b * C * HW + tok0;
    uint32_t ah[4][4];
    {
        const int row0 = wtok + g, row1 = row0 + 8;
        #pragma unroll
        for (int kt = 0; kt < 4; kt++) {
            #pragma unroll
            for (int half = 0; half < 2; half++) {
                int c0 = kt * 16 + tq * 2 + half * 8;
                float v00 = xg[(size_t)c0 * HW + row0];
                float v01 = xg[(size_t)(c0 + 1) * HW + row0];
                float v10 = xg[(size_t)c0 * HW + row1];
                float v11 = xg[(size_t)(c0 + 1) * HW + row1];
                ah[kt][half * 2]     = packh2(v00, v01);
                ah[kt][half * 2 + 1] = packh2(v10, v11);
            }
        }
    }

    float yacc[8][4];
    #pragma unroll
    for (int nt = 0; nt < 8; nt++)
        #pragma unroll
        for (int q = 0; q < 4; q++) yacc[nt][q] = 0.f;
    float zacc[2] = {0.f, 0.f};

    const uint32_t brow = (uint32_t)(lane & 7) * 144 + (uint32_t)((lane >> 3) * 16);

    for (int ci = 0; ci < 8; ci++) {
        if (ci < 7) asm volatile("cp.async.wait_group 1;" ::: "memory");
        else        asm volatile("cp.async.wait_group 0;" ::: "memory");
        __syncthreads();

        const uint32_t stg = smb + WB_OFF + (uint32_t)((ci & 1) * 18432);
        const uint32_t Wh = stg, Mh = stg + 9216;
        const float* sbp = (const float*)(S + SB_OFF) + ci * 64;

        // ---- GEMM2 + fused exp ----
        uint32_t eh[8], eh2[8];
        #pragma unroll
        for (int nt = 0; nt < 8; nt++) {
            uint32_t radr = (uint32_t)(nt * 8) * 144 + brow;
            uint32_t bh[8];
            LDSM4(bh,     Wh + radr);
            LDSM4(bh + 4, Wh + radr + 64);
            float sc[4] = {0.f, 0.f, 0.f, 0.f};
            #pragma unroll
            for (int kt = 0; kt < 4; kt++)
                mma16816(sc, ah[kt][0], ah[kt][1], ah[kt][2], ah[kt][3], bh[2 * kt], bh[2 * kt + 1]);
            float sbx = sbp[nt * 8 + 2 * tq];
            float sby = sbp[nt * 8 + 2 * tq + 1];
            float e0 = ex2f(sc[0] + sbx);
            float e1 = ex2f(sc[1] + sby);
            float e2 = ex2f(sc[2] + sbx);
            float e3 = ex2f(sc[3] + sby);
            zacc[0] += e0 + e1;
            zacc[1] += e2 + e3;
            eh[nt]  = packh2(e0, e1);
            eh2[nt] = packh2(e2, e3);
        }

        // ---- GEMM3: y += E @ mb2^T ----
        #pragma unroll
        for (int nt = 0; nt < 8; nt++) {
            uint32_t radr = (uint32_t)(nt * 8) * 144 + brow;
            uint32_t mh[8];
            LDSM4(mh,     Mh + radr);
            LDSM4(mh + 4, Mh + radr + 64);
            #pragma unroll
            for (int kt = 0; kt < 4; kt++) {
                mma16816(yacc[nt], eh[2 * kt], eh2[2 * kt], eh[2 * kt + 1], eh2[2 * kt + 1],
                         mh[2 * kt], mh[2 * kt + 1]);
            }
        }

        __syncthreads();
        if (ci + 2 < 8) {
            prefetch_chunk(ci + 2, ci & 1, b, tid, smb);
            asm volatile("cp.async.commit_group;" ::: "memory");
        }
    }

    // row-sum Z over quad lanes
    #pragma unroll
    for (int q = 0; q < 2; q++) {
        zacc[q] += __shfl_xor_sync(0xFFFFFFFFu, zacc[q], 1);
        zacc[q] += __shfl_xor_sync(0xFFFFFFFFu, zacc[q], 2);
    }
    float* ZRp = (float*)(S + ZR_OFF);
    if (tq == 0) {
        ZRp[wtok + g]     = zacc[0];
        ZRp[wtok + 8 + g] = zacc[1];
    }
    __syncwarp();
    float iz0 = 1.f / ZRp[wtok + g];
    float iz1 = 1.f / ZRp[wtok + 8 + g];

    // stage y to smem [o][tok] (pad 132) for coalesced output
    float* YS = (float*)S;
    __syncthreads();
    {
        int r0 = wtok + g;
        #pragma unroll
        for (int nt = 0; nt < 8; nt++) {
            int o0 = nt * 8 + 2 * tq;
            YS[o0 * 132 + r0]           = yacc[nt][0] * iz0;
            YS[(o0 + 1) * 132 + r0]     = yacc[nt][1] * iz0;
            YS[o0 * 132 + r0 + 8]       = yacc[nt][2] * iz1;
            YS[(o0 + 1) * 132 + r0 + 8] = yacc[nt][3] * iz1;
        }
    }
    __syncthreads();

    // out = y + wz_b + residual, coalesced float4
    const float* wzp = (const float*)(S + WZB_OFF);
    float* og = out + (size_t)b * C * HW + tok0;
    #pragma unroll
    for (int it = 0; it < 8; it++) {
        int i = tid + it * 256;
        int o = i >> 5, t32 = i & 31;
        float4 ys = *(const float4*)(YS + o * 132 + t32 * 4);
        float4 xr = *(const float4*)(xg + (size_t)o * HW + t32 * 4);
        float wb = wzp[o];
        float4 r;
        r.x = ys.x + xr.x + wb;
        r.y = ys.y + xr.y + wb;
        r.z = ys.z + xr.z + wb;
        r.w = ys.w + xr.w + wb;
        *(float4*)(og + (size_t)o * HW + t32 * 4) = r;
    }
}

// ---------------------------------------------------------------------------
extern "C" void kernel_launch(void* const* d_in, const int* in_sizes, int n_in,
                              void* d_out, int out_size) {
    const float* x     = (const float*)d_in[0];
    const float* mb    = (const float*)d_in[1];
    const float* phi_w = (const float*)d_in[2];
    const float* phi_b = (const float*)d_in[3];
    const float* gn_w  = (const float*)d_in[4];
    const float* gn_b  = (const float*)d_in[5];
    const float* wz_w  = (const float*)d_in[6];
    const float* wz_b  = (const float*)d_in[7];
    float* out = (float*)d_out;

    cudaFuncSetAttribute(fused_main_kernel,
                         cudaFuncAttributeMaxDynamicSharedMemorySize, SMEM_TOTAL);
    cudaFuncSetAttribute(merged_prep_kernel,
                         cudaFuncAttributeMaxDynamicSharedMemorySize, MP_FLOATS * 4);

    gn_stats_kernel<<<NB * NG, 256>>>(x);
    prep0_kernel<<<NB, C>>>(phi_w, phi_b, gn_w, gn_b);
    merged_prep_kernel<<<KCB / 64, 256, MP_FLOATS * 4>>>(phi_w, wz_w, mb);

    dim3 grid(HW / TOKT, NB);
    fused_main_kernel<<<grid, THREADS, SMEM_TOTAL>>>(x, out, wz_b);
}